// round 15
// baseline (speedup 1.0000x reference)
#include <cuda_runtime.h>
#include <cstdint>
#include <cstddef>

#define NPTS 4096
#define DIM  64
#define NBLK 128     // persistent blocks (<=148 SMs, 1 block/SM -> co-resident)
#define TPB  1024

// ---------------------------------------------------------------------------
// Scratch (allocation-free rule: __device__ globals)
// ---------------------------------------------------------------------------
__device__ float g_sq[NPTS];
__device__ float g_d2[(size_t)NPTS * NPTS];          // 64 MB f32, L2-resident
__device__ float g_len[NPTS];                        // MST edge lengths
__device__ unsigned long long g_gmin[NPTS * 128];    // 4 MB per-(row,32col) mins
__device__ unsigned long long g_best[3][NPTS];       // triple-buffered comp keys
__device__ int          g_bar_cnt;
__device__ volatile int g_bar_gen;

static __device__ __forceinline__ float inf32() { return __int_as_float(0x7f800000); }
static __device__ __forceinline__ unsigned long long umin64(unsigned long long a,
                                                            unsigned long long b) {
    return a < b ? a : b;
}
// global key = (f32 d2 bits << 24) | (min(u,v)<<12) | max(u,v)
// globally unique; identical from both endpoints => only mutual 2-cycles.
static __device__ __forceinline__ unsigned long long mkkey(unsigned wbits,
                                                           unsigned a, unsigned b) {
    unsigned lo = min(a, b), hi = max(a, b);
    return ((unsigned long long)wbits << 24) | (lo << 12) | hi;
}
// local row key (w32<<32|j) of row c -> global canonical key
static __device__ __forceinline__ unsigned long long loc2key(unsigned long long ck,
                                                             unsigned c) {
    if (ck == ~0ull) return ~0ull;
    return mkkey((unsigned)(ck >> 32), c, (unsigned)(ck & 0xFFFu));
}

static __device__ __forceinline__ void gridbar() {
    __syncthreads();
    if (threadIdx.x == 0) {
        __threadfence();
        int gen = g_bar_gen;
        if (atomicAdd(&g_bar_cnt, 1) == NBLK - 1) {
            g_bar_cnt = 0;
            __threadfence();
            g_bar_gen = gen + 1;
        } else {
            while (g_bar_gen == gen) { }
        }
        __threadfence();
    }
    __syncthreads();
}

// ---------------------------------------------------------------------------
// Kernel 1: warp-per-row squared norms + clear best buffers + barrier reset
// ---------------------------------------------------------------------------
__global__ void k_init(const float* __restrict__ p) {
    const int t   = threadIdx.x;
    const int gt  = blockIdx.x * TPB + t;
    const int row = gt >> 5;
    const int ln  = gt & 31;

    if (gt == 0) { g_bar_cnt = 0; g_bar_gen = 0; }
    if (gt < 3 * NPTS) ((unsigned long long*)g_best)[gt] = ~0ull;

    float2 v = *(const float2*)(p + (size_t)row * DIM + ln * 2);
    float acc = fmaf(v.x, v.x, v.y * v.y);
#pragma unroll
    for (int s = 16; s > 0; s >>= 1)
        acc += __shfl_down_sync(0xFFFFFFFFu, acc, s);
    if (ln == 0) g_sq[row] = acc;
}

// ---------------------------------------------------------------------------
// Kernel 2: f32 d2 matrix (128x128 tile, 8x8/thread, packed f32x2 FMA) with
// fused per-(row, 32-col granule) min epilogue -> g_gmin (w32<<32|j).
// Granule = 4 consecutive tx threads (32 cols); reduce via width-4 shuffles.
// ---------------------------------------------------------------------------
__global__ void k_d2(const float* __restrict__ p) {
    __shared__ float As[32][128];
    __shared__ float Bs[32][128];

    const int t  = threadIdx.x;          // 0..255
    const int tx = t & 15;
    const int ty = t >> 4;
    const int i0 = blockIdx.y * 128;
    const int j0 = blockIdx.x * 128;

    const int lr = t >> 1;
    const int lc = (t & 1) * 16;

    unsigned long long acc2[8][4];
#pragma unroll
    for (int m = 0; m < 8; m++)
#pragma unroll
        for (int n = 0; n < 4; n++) acc2[m][n] = 0ull;

#pragma unroll
    for (int k0 = 0; k0 < DIM; k0 += 32) {
#pragma unroll
        for (int q = 0; q < 4; q++) {
            int c = lc + q * 4;
            float4 va = *(const float4*)(p + (size_t)(i0 + lr) * DIM + k0 + c);
            As[c + 0][lr] = va.x; As[c + 1][lr] = va.y;
            As[c + 2][lr] = va.z; As[c + 3][lr] = va.w;
            float4 vb = *(const float4*)(p + (size_t)(j0 + lr) * DIM + k0 + c);
            Bs[c + 0][lr] = vb.x; Bs[c + 1][lr] = vb.y;
            Bs[c + 2][lr] = vb.z; Bs[c + 3][lr] = vb.w;
        }
        __syncthreads();

#pragma unroll
        for (int k = 0; k < 32; k++) {
            uint4 a0 = *(const uint4*)&As[k][ty * 8];
            uint4 a1 = *(const uint4*)&As[k][ty * 8 + 4];
            unsigned au[8] = {a0.x, a0.y, a0.z, a0.w, a1.x, a1.y, a1.z, a1.w};
            ulonglong2 b0 = *(const ulonglong2*)&Bs[k][tx * 8];
            ulonglong2 b1 = *(const ulonglong2*)&Bs[k][tx * 8 + 4];
            unsigned long long bp[4] = {b0.x, b0.y, b1.x, b1.y};
#pragma unroll
            for (int m = 0; m < 8; m++) {
                unsigned long long ap;
                asm("mov.b64 %0, {%1, %1};" : "=l"(ap) : "r"(au[m]));
#pragma unroll
                for (int n = 0; n < 4; n++)
                    asm("fma.rn.f32x2 %0, %1, %2, %0;"
                        : "+l"(acc2[m][n]) : "l"(ap), "l"(bp[n]));
            }
        }
        __syncthreads();
    }

    float sqi[8], sqj[8];
#pragma unroll
    for (int m = 0; m < 8; m++) sqi[m] = g_sq[i0 + ty * 8 + m];
#pragma unroll
    for (int n = 0; n < 8; n++) sqj[n] = g_sq[j0 + tx * 8 + n];

#pragma unroll
    for (int m = 0; m < 8; m++) {
        const int row = i0 + ty * 8 + m;
        float o[8];
#pragma unroll
        for (int n = 0; n < 4; n++) {
            unsigned lo, hi;
            asm("mov.b64 {%0, %1}, %2;" : "=r"(lo), "=r"(hi) : "l"(acc2[m][n]));
            float d0 = __uint_as_float(lo), d1 = __uint_as_float(hi);
            o[2 * n + 0] = fmaxf(sqi[m] + sqj[2 * n + 0] - 2.f * d0, 0.f);
            o[2 * n + 1] = fmaxf(sqi[m] + sqj[2 * n + 1] - 2.f * d1, 0.f);
        }
        float* dst = g_d2 + (size_t)row * NPTS + j0 + tx * 8;
        *(float4*)(dst)     = *(float4*)(o);
        *(float4*)(dst + 4) = *(float4*)(o + 4);

        // fused per-(row, 32-col granule) min (w<<32|j), diag excluded
        unsigned long long key = ~0ull;
#pragma unroll
        for (int n = 0; n < 8; n++) {
            unsigned jj = (unsigned)(j0 + tx * 8 + n);
            if (jj != (unsigned)row)
                key = umin64(key, ((unsigned long long)__float_as_uint(o[n]) << 32) | jj);
        }
        key = umin64(key, __shfl_down_sync(0xFFFFFFFFu, key, 2, 4));
        key = umin64(key, __shfl_down_sync(0xFFFFFFFFu, key, 1, 4));
        if ((tx & 3) == 0)
            g_gmin[row * 128 + (j0 >> 5) + (tx >> 2)] = key;
    }
}

// ---------------------------------------------------------------------------
// Kernel 3: persistent Boruvka + sort. Selection per warp/row via 128
// granule-min entries (lane l owns granules l, 32+l, 64+l, 96+l):
// out-of-comp entries are EXACT granule out-comp minima; in-comp entries are
// lower bounds; rescans are 128 B warp-cooperative, with write-back. Exact
// selection. One grid barrier per round; hook over active components in smem.
// ---------------------------------------------------------------------------
__global__ void __launch_bounds__(TPB, 1) k_mst(float* __restrict__ out) {
    __shared__ unsigned short comp[NPTS];     // 8 KB persistent labels
    __shared__ int par[NPTS];                 // 16 KB; reused as float sort buf
    __shared__ unsigned short act[2][NPTS];   // 16 KB ping-pong active comps
    __shared__ int s_na2;                     // next active count
    __shared__ int s_cnt;                     // block0 edge counter

    const int t    = threadIdx.x;
    const int wid  = t >> 5;
    const int lane = t & 31;
    const int row  = blockIdx.x * 32 + wid;

    for (int i = t; i < NPTS; i += TPB) {
        comp[i] = (unsigned short)i;
        act[0][i] = (unsigned short)i;
    }
    if (t == 0) s_cnt = 0;
    __syncthreads();

    // lane holds 4 granule-min entries for `row` (granules q*32+lane)
    unsigned long long e[4];
    {
        const unsigned long long* gm = g_gmin + row * 128;
#pragma unroll
        for (int q = 0; q < 4; q++) e[q] = gm[q * 32 + lane];
    }
    int na = NPTS;

    for (int k = 0; k < 12; k++) {
        const int pp = k & 1;

        // ---- selection via granule-min bounds ----
        {
            const unsigned myc = comp[row];
            bool oc[4];
            unsigned long long cand = ~0ull;
#pragma unroll
            for (int q = 0; q < 4; q++) {
                unsigned ej = (unsigned)(e[q] & 0xFFFu);
                oc[q] = comp[ej] != myc;
                if (oc[q]) cand = umin64(cand, e[q]);
            }
#pragma unroll
            for (int s = 16; s > 0; s >>= 1)
                cand = umin64(cand, __shfl_xor_sync(0xFFFFFFFFu, cand, s));

#pragma unroll
            for (int q = 0; q < 4; q++) {
                unsigned mask = __ballot_sync(0xFFFFFFFFu, !oc[q] && e[q] < cand);
                while (mask) {
                    int g = __ffs(mask) - 1;
                    mask &= mask - 1;
                    unsigned long long eb = __shfl_sync(0xFFFFFFFFu, e[q], g);
                    if (eb >= cand) continue;          // cand tightened: prune
                    const int gid = q * 32 + g;
                    const float* r = g_d2 + (size_t)row * NPTS + gid * 32;
                    unsigned long long m = ~0ull;
                    unsigned jj = (unsigned)(gid * 32 + lane);
                    if (comp[jj] != myc)
                        m = ((unsigned long long)__float_as_uint(r[lane]) << 32) | jj;
#pragma unroll
                    for (int s = 16; s > 0; s >>= 1)
                        m = umin64(m, __shfl_xor_sync(0xFFFFFFFFu, m, s));
                    if (lane == g) e[q] = m;           // write-back (exact now)
                    cand = umin64(cand, m);
                }
            }
            if (lane == 0 && cand != ~0ull)
                atomicMin(&g_best[k % 3][myc], loc2key(cand, (unsigned)row));
        }
        gridbar();

        // ---- hook over ACTIVE components (all blocks, redundant) ----
        const unsigned long long* B = g_best[k % 3];
        for (int idx = t; idx < na; idx += TPB) { int c = act[pp][idx]; par[c] = c; }
        if (t == 0) s_na2 = 0;
        __syncthreads();

        for (int idx = t; idx < na; idx += TPB) {
            int c = act[pp][idx];
            unsigned long long key = B[c];
            bool isroot = false;
            if (key != ~0ull) {
                unsigned id = (unsigned)(key & 0xFFFFFFu);
                int u = (int)(id >> 12), v = (int)(id & 0xFFFu);
                int cu = comp[u], cv = comp[v];
                int other = (cu == c) ? cv : cu;
                bool mutual = (B[other] == key);
                if (!mutual)        par[c] = other;
                else if (c > other) par[c] = other;
                else                isroot = true;
                if (blockIdx.x == 0 && (!mutual || c < other)) {
                    int e2 = atomicAdd(&s_cnt, 1);
                    g_len[e2] = sqrtf(__uint_as_float((unsigned)(key >> 24)));
                }
            } else {
                isroot = true;
            }
            if (isroot) {
                int pos = atomicAdd(&s_na2, 1);
                act[pp ^ 1][pos] = (unsigned short)c;
            }
        }
        __syncthreads();

        // pointer jumping over active list, early exit on convergence
        for (int it = 0; it < 12; it++) {
            int chg = 0;
            for (int idx = t; idx < na; idx += TPB) {
                int c = act[pp][idx];
                int p1 = par[c];
                int p2 = par[p1];
                if (p2 != p1) { par[c] = p2; chg = 1; }
            }
            if (!__syncthreads_or(chg)) break;
        }

        // relabel all vertices + clear this block's slice of buffer (k+2)%3
        for (int i = t; i < NPTS; i += TPB)
            comp[i] = (unsigned short)par[comp[i]];
        if (t < 32) g_best[(k + 2) % 3][blockIdx.x * 32 + t] = ~0ull;
        __syncthreads();

        na = s_na2;
        if (na <= 1) break;
    }

    // ---- block 0: bitonic sort (pad one +inf), write output ----
    if (blockIdx.x != 0) return;
    __syncthreads();
    float* sh = (float*)par;
    for (int m = t; m < NPTS; m += TPB)
        sh[m] = (m < NPTS - 1) ? g_len[m] : inf32();
    __syncthreads();

    for (int kk = 2; kk <= NPTS; kk <<= 1) {
        for (int j = kk >> 1; j > 0; j >>= 1) {
#pragma unroll
            for (int tt = 0; tt < 2; tt++) {
                int u = t + tt * TPB;
                int i = ((u & ~(j - 1)) << 1) | (u & (j - 1));
                int l = i | j;
                float a = sh[i], c = sh[l];
                bool up = (i & kk) == 0;
                if ((a > c) == up) { sh[i] = c; sh[l] = a; }
            }
            __syncthreads();
        }
    }
    for (int m = t; m < NPTS - 1; m += TPB) out[m] = sh[m];
}

// ---------------------------------------------------------------------------
extern "C" void kernel_launch(void* const* d_in, const int* in_sizes, int n_in,
                              void* d_out, int out_size) {
    (void)in_sizes; (void)n_in; (void)out_size;
    const float* points = (const float*)d_in[0];
    float* out = (float*)d_out;

    k_init<<<NPTS * 32 / TPB, TPB>>>(points);            // 128 x 1024
    k_d2<<<dim3(NPTS / 128, NPTS / 128), 256>>>(points); // 32x32 x 256
    k_mst<<<NBLK, TPB>>>(out);
}

// round 16
// speedup vs baseline: 1.1444x; 1.1444x over previous
#include <cuda_runtime.h>
#include <cstdint>
#include <cstddef>

#define NPTS 4096
#define DIM  64
#define NBLK 128     // persistent blocks (<=148 SMs, 1 block/SM -> co-resident)
#define TPB  1024

// ---------------------------------------------------------------------------
// Scratch (allocation-free rule: __device__ globals)
// ---------------------------------------------------------------------------
__device__ float g_sq[NPTS];
__device__ float g_d2[(size_t)NPTS * NPTS];          // 64 MB f32, L2-resident
__device__ float g_len[NPTS];                        // MST edge lengths
__device__ unsigned long long g_bmin[NPTS * 32];     // per-(row,128col) mins
__device__ unsigned long long g_best[3][NPTS];       // triple-buffered comp keys
__device__ volatile int g_bar_flag[NBLK];            // per-block arrival flags
__device__ volatile int g_bar_gen;                   // release generation

static __device__ __forceinline__ float inf32() { return __int_as_float(0x7f800000); }
static __device__ __forceinline__ unsigned long long umin64(unsigned long long a,
                                                            unsigned long long b) {
    return a < b ? a : b;
}
// global key = (f32 d2 bits << 24) | (min(u,v)<<12) | max(u,v)
// globally unique; identical from both endpoints => only mutual 2-cycles.
static __device__ __forceinline__ unsigned long long mkkey(unsigned wbits,
                                                           unsigned a, unsigned b) {
    unsigned lo = min(a, b), hi = max(a, b);
    return ((unsigned long long)wbits << 24) | (lo << 12) | hi;
}
// local row key (w32<<32|j) of row c -> global canonical key
static __device__ __forceinline__ unsigned long long loc2key(unsigned long long ck,
                                                             unsigned c) {
    if (ck == ~0ull) return ~0ull;
    return mkkey((unsigned)(ck >> 32), c, (unsigned)(ck & 0xFFFFu));
}

// Flag-array grid barrier: parallel arrival stores, block-0 parallel poll,
// single release word. gen must be strictly increasing per call (per launch).
static __device__ __forceinline__ void gridbar(int gen) {
    __syncthreads();
    if (blockIdx.x == 0) {
        if (threadIdx.x > 0 && threadIdx.x < NBLK)
            while (g_bar_flag[threadIdx.x] < gen) { }
        __syncthreads();
        if (threadIdx.x == 0) {
            __threadfence();
            g_bar_gen = gen;
        }
    } else {
        if (threadIdx.x == 0) {
            __threadfence();
            g_bar_flag[blockIdx.x] = gen;
            while (g_bar_gen < gen) { }
            __threadfence();
        }
    }
    __syncthreads();
}

// ---------------------------------------------------------------------------
// Kernel 1: warp-per-row squared norms + clear best buffers + barrier reset
// ---------------------------------------------------------------------------
__global__ void k_init(const float* __restrict__ p) {
    const int t   = threadIdx.x;
    const int gt  = blockIdx.x * TPB + t;
    const int row = gt >> 5;
    const int ln  = gt & 31;

    if (gt < NBLK) g_bar_flag[gt] = 0;
    if (gt == 0) g_bar_gen = 0;
    if (gt < 3 * NPTS) ((unsigned long long*)g_best)[gt] = ~0ull;

    float2 v = *(const float2*)(p + (size_t)row * DIM + ln * 2);
    float acc = fmaf(v.x, v.x, v.y * v.y);
#pragma unroll
    for (int s = 16; s > 0; s >>= 1)
        acc += __shfl_down_sync(0xFFFFFFFFu, acc, s);
    if (ln == 0) g_sq[row] = acc;
}

// ---------------------------------------------------------------------------
// Kernel 2: f32 d2 matrix (128x128 tile, 8x8/thread, packed f32x2 FMA) with
// fused per-(row, col-block) min epilogue -> g_bmin (w32<<32|j).
// ---------------------------------------------------------------------------
__global__ void k_d2(const float* __restrict__ p) {
    __shared__ float As[32][128];
    __shared__ float Bs[32][128];

    const int t  = threadIdx.x;          // 0..255
    const int tx = t & 15;
    const int ty = t >> 4;
    const int i0 = blockIdx.y * 128;
    const int j0 = blockIdx.x * 128;

    const int lr = t >> 1;
    const int lc = (t & 1) * 16;

    unsigned long long acc2[8][4];
#pragma unroll
    for (int m = 0; m < 8; m++)
#pragma unroll
        for (int n = 0; n < 4; n++) acc2[m][n] = 0ull;

#pragma unroll
    for (int k0 = 0; k0 < DIM; k0 += 32) {
#pragma unroll
        for (int q = 0; q < 4; q++) {
            int c = lc + q * 4;
            float4 va = *(const float4*)(p + (size_t)(i0 + lr) * DIM + k0 + c);
            As[c + 0][lr] = va.x; As[c + 1][lr] = va.y;
            As[c + 2][lr] = va.z; As[c + 3][lr] = va.w;
            float4 vb = *(const float4*)(p + (size_t)(j0 + lr) * DIM + k0 + c);
            Bs[c + 0][lr] = vb.x; Bs[c + 1][lr] = vb.y;
            Bs[c + 2][lr] = vb.z; Bs[c + 3][lr] = vb.w;
        }
        __syncthreads();

#pragma unroll
        for (int k = 0; k < 32; k++) {
            uint4 a0 = *(const uint4*)&As[k][ty * 8];
            uint4 a1 = *(const uint4*)&As[k][ty * 8 + 4];
            unsigned au[8] = {a0.x, a0.y, a0.z, a0.w, a1.x, a1.y, a1.z, a1.w};
            ulonglong2 b0 = *(const ulonglong2*)&Bs[k][tx * 8];
            ulonglong2 b1 = *(const ulonglong2*)&Bs[k][tx * 8 + 4];
            unsigned long long bp[4] = {b0.x, b0.y, b1.x, b1.y};
#pragma unroll
            for (int m = 0; m < 8; m++) {
                unsigned long long ap;
                asm("mov.b64 %0, {%1, %1};" : "=l"(ap) : "r"(au[m]));
#pragma unroll
                for (int n = 0; n < 4; n++)
                    asm("fma.rn.f32x2 %0, %1, %2, %0;"
                        : "+l"(acc2[m][n]) : "l"(ap), "l"(bp[n]));
            }
        }
        __syncthreads();
    }

    float sqi[8], sqj[8];
#pragma unroll
    for (int m = 0; m < 8; m++) sqi[m] = g_sq[i0 + ty * 8 + m];
#pragma unroll
    for (int n = 0; n < 8; n++) sqj[n] = g_sq[j0 + tx * 8 + n];

#pragma unroll
    for (int m = 0; m < 8; m++) {
        const int row = i0 + ty * 8 + m;
        float o[8];
#pragma unroll
        for (int n = 0; n < 4; n++) {
            unsigned lo, hi;
            asm("mov.b64 {%0, %1}, %2;" : "=r"(lo), "=r"(hi) : "l"(acc2[m][n]));
            float d0 = __uint_as_float(lo), d1 = __uint_as_float(hi);
            o[2 * n + 0] = fmaxf(sqi[m] + sqj[2 * n + 0] - 2.f * d0, 0.f);
            o[2 * n + 1] = fmaxf(sqi[m] + sqj[2 * n + 1] - 2.f * d1, 0.f);
        }
        float* dst = g_d2 + (size_t)row * NPTS + j0 + tx * 8;
        *(float4*)(dst)     = *(float4*)(o);
        *(float4*)(dst + 4) = *(float4*)(o + 4);

        // fused per-(row, 128-col block) min (w<<32|j), diag excluded
        unsigned long long key = ~0ull;
#pragma unroll
        for (int n = 0; n < 8; n++) {
            unsigned jj = (unsigned)(j0 + tx * 8 + n);
            if (jj != (unsigned)row)
                key = umin64(key, ((unsigned long long)__float_as_uint(o[n]) << 32) | jj);
        }
#pragma unroll
        for (int s = 8; s > 0; s >>= 1)
            key = umin64(key, __shfl_down_sync(0xFFFFFFFFu, key, s, 16));
        if (tx == 0) g_bmin[row * 32 + blockIdx.x] = key;
    }
}

// ---------------------------------------------------------------------------
// Kernel 3: persistent Boruvka + distributed rank-sort.
// Selection per warp/row via block-min bounds (exact == full-scan); one grid
// barrier per round; hook over active components, all blocks redundantly in
// their own shared memory. After the last round all blocks rank-sort the
// 4095 lengths cooperatively (one edge per warp).
// ---------------------------------------------------------------------------
__global__ void __launch_bounds__(TPB, 1) k_mst(float* __restrict__ out) {
    __shared__ unsigned short comp[NPTS];     // 8 KB persistent labels
    __shared__ int par[NPTS];                 // 16 KB; reused as rank-sort buf
    __shared__ unsigned short act[2][NPTS];   // 16 KB ping-pong active comps
    __shared__ int s_na2;                     // next active count
    __shared__ int s_cnt;                     // block0 edge counter

    const int t    = threadIdx.x;
    const int wid  = t >> 5;
    const int lane = t & 31;
    const int row  = blockIdx.x * 32 + wid;

    for (int i = t; i < NPTS; i += TPB) {
        comp[i] = (unsigned short)i;
        act[0][i] = (unsigned short)i;
    }
    if (t == 0) s_cnt = 0;
    __syncthreads();

    int na = NPTS;
    int gen = 0;

    for (int k = 0; k < 12; k++) {
        const int pp = k & 1;

        // ---- selection via block-min bounds ----
        {
            const unsigned myc = comp[row];
            unsigned long long e = g_bmin[row * 32 + lane];
            unsigned ej = (unsigned)(e & 0xFFFFu);
            bool oc = comp[ej] != myc;                 // partner out-of-comp?
            unsigned long long cand = oc ? e : ~0ull;
#pragma unroll
            for (int s = 16; s > 0; s >>= 1)
                cand = umin64(cand, __shfl_xor_sync(0xFFFFFFFFu, cand, s));

            unsigned scanmask = __ballot_sync(0xFFFFFFFFu, !oc && e < cand);
            unsigned long long best = cand;
            while (scanmask) {
                int b = __ffs(scanmask) - 1;
                scanmask &= scanmask - 1;
                const float* r = g_d2 + (size_t)row * NPTS + b * 128;
#pragma unroll
                for (int s2 = 0; s2 < 4; s2++) {
                    int jj = s2 * 32 + lane;
                    if (comp[b * 128 + jj] != myc) {
                        unsigned long long kk =
                            ((unsigned long long)__float_as_uint(r[jj]) << 32) |
                            (unsigned)(b * 128 + jj);
                        best = umin64(best, kk);
                    }
                }
            }
#pragma unroll
            for (int s = 16; s > 0; s >>= 1)
                best = umin64(best, __shfl_down_sync(0xFFFFFFFFu, best, s));
            if (lane == 0 && best != ~0ull)
                atomicMin(&g_best[k % 3][myc], loc2key(best, (unsigned)row));
        }
        gridbar(++gen);

        // ---- hook over ACTIVE components (all blocks, redundant) ----
        const unsigned long long* B = g_best[k % 3];
        for (int idx = t; idx < na; idx += TPB) { int c = act[pp][idx]; par[c] = c; }
        if (t == 0) s_na2 = 0;
        __syncthreads();

        for (int idx = t; idx < na; idx += TPB) {
            int c = act[pp][idx];
            unsigned long long key = B[c];
            bool isroot = false;
            if (key != ~0ull) {
                unsigned id = (unsigned)(key & 0xFFFFFFu);
                int u = (int)(id >> 12), v = (int)(id & 0xFFFu);
                int cu = comp[u], cv = comp[v];
                int other = (cu == c) ? cv : cu;
                bool mutual = (B[other] == key);
                if (!mutual)        par[c] = other;
                else if (c > other) par[c] = other;
                else                isroot = true;
                if (blockIdx.x == 0 && (!mutual || c < other)) {
                    int e = atomicAdd(&s_cnt, 1);
                    g_len[e] = sqrtf(__uint_as_float((unsigned)(key >> 24)));
                }
            } else {
                isroot = true;
            }
            if (isroot) {
                int pos = atomicAdd(&s_na2, 1);
                act[pp ^ 1][pos] = (unsigned short)c;
            }
        }
        __syncthreads();

        // pointer jumping over active list, early exit on convergence
        for (int it = 0; it < 12; it++) {
            int chg = 0;
            for (int idx = t; idx < na; idx += TPB) {
                int c = act[pp][idx];
                int p1 = par[c];
                int p2 = par[p1];
                if (p2 != p1) { par[c] = p2; chg = 1; }
            }
            if (!__syncthreads_or(chg)) break;
        }

        // relabel all vertices + clear this block's slice of buffer (k+2)%3
        for (int i = t; i < NPTS; i += TPB)
            comp[i] = (unsigned short)par[comp[i]];
        if (t < 32) g_best[(k + 2) % 3][blockIdx.x * 32 + t] = ~0ull;
        __syncthreads();

        na = s_na2;
        if (na <= 1) break;
    }

    // ---- distributed rank-sort: all blocks alive, one edge per warp ----
    gridbar(++gen);                        // g_len complete + visible

    float* sh = (float*)par;               // stage lengths in shared
    for (int i = t; i < NPTS - 1; i += TPB) sh[i] = g_len[i];
    __syncthreads();

    const int e = blockIdx.x * 32 + wid;   // 128 blocks x 32 warps = 4096
    if (e < NPTS - 1) {
        unsigned my = __float_as_uint(sh[e]);   // nonneg floats: u32 order
        int r = 0;
        for (int s = lane; s < NPTS - 1; s += 32) {   // stride 32: no conflicts
            unsigned o = __float_as_uint(sh[s]);
            r += (o < my) || (o == my && s < e);
        }
#pragma unroll
        for (int s = 16; s > 0; s >>= 1)
            r += __shfl_down_sync(0xFFFFFFFFu, r, s);
        if (lane == 0) out[r] = __uint_as_float(my);
    }
}

// ---------------------------------------------------------------------------
extern "C" void kernel_launch(void* const* d_in, const int* in_sizes, int n_in,
                              void* d_out, int out_size) {
    (void)in_sizes; (void)n_in; (void)out_size;
    const float* points = (const float*)d_in[0];
    float* out = (float*)d_out;

    k_init<<<NPTS * 32 / TPB, TPB>>>(points);            // 128 x 1024
    k_d2<<<dim3(NPTS / 128, NPTS / 128), 256>>>(points); // 32x32 x 256
    k_mst<<<NBLK, TPB>>>(out);
}

// round 17
// speedup vs baseline: 1.1700x; 1.0224x over previous
#include <cuda_runtime.h>
#include <cstdint>
#include <cstddef>

#define NPTS 4096
#define DIM  64
#define NBLK 128     // persistent blocks (<=148 SMs, 1 block/SM -> co-resident)
#define TPB  1024

// ---------------------------------------------------------------------------
// Scratch (allocation-free rule: __device__ globals)
// ---------------------------------------------------------------------------
__device__ float g_d2[(size_t)NPTS * NPTS];          // 64 MB f32, L2-resident
__device__ float g_len[NPTS];                        // MST edge lengths
__device__ unsigned long long g_bmin[NPTS * 32];     // per-(row,128col) mins
__device__ unsigned long long g_best[3][NPTS];       // triple-buffered comp keys
__device__ volatile int g_bar_flag[NBLK];            // per-block arrival flags
__device__ volatile int g_bar_gen;                   // release generation

static __device__ __forceinline__ unsigned long long umin64(unsigned long long a,
                                                            unsigned long long b) {
    return a < b ? a : b;
}
// global key = (f32 d2 bits << 24) | (min(u,v)<<12) | max(u,v)
// globally unique; identical from both endpoints => only mutual 2-cycles.
static __device__ __forceinline__ unsigned long long mkkey(unsigned wbits,
                                                           unsigned a, unsigned b) {
    unsigned lo = min(a, b), hi = max(a, b);
    return ((unsigned long long)wbits << 24) | (lo << 12) | hi;
}
// local row key (w32<<32|j) of row c -> global canonical key
static __device__ __forceinline__ unsigned long long loc2key(unsigned long long ck,
                                                             unsigned c) {
    if (ck == ~0ull) return ~0ull;
    return mkkey((unsigned)(ck >> 32), c, (unsigned)(ck & 0xFFFFu));
}

// Flag-array grid barrier: parallel arrival stores, block-0 parallel poll,
// single release word. gen must be strictly increasing per call (per launch).
static __device__ __forceinline__ void gridbar(int gen) {
    __syncthreads();
    if (blockIdx.x == 0) {
        if (threadIdx.x > 0 && threadIdx.x < NBLK)
            while (g_bar_flag[threadIdx.x] < gen) { }
        __syncthreads();
        if (threadIdx.x == 0) {
            __threadfence();
            g_bar_gen = gen;
        }
    } else {
        if (threadIdx.x == 0) {
            __threadfence();
            g_bar_flag[blockIdx.x] = gen;
            while (g_bar_gen < gen) { }
            __threadfence();
        }
    }
    __syncthreads();
}

// ---------------------------------------------------------------------------
// Kernel 1: f32 d2 matrix (128x128 tile, 8x8/thread, packed f32x2 FMA) with
//  - row norms accumulated in REGISTERS during the load loop (no init kernel)
//  - fused per-(row, col-block) min epilogue -> g_bmin (w32<<32|j)
//  - housekeeping on the by==0 row: g_best clear, barrier state reset
// ---------------------------------------------------------------------------
__global__ void k_d2(const float* __restrict__ p) {
    __shared__ float As[32][128];
    __shared__ float Bs[32][128];
    __shared__ float sAsq[128];
    __shared__ float sBsq[128];

    const int t  = threadIdx.x;          // 0..255
    const int tx = t & 15;
    const int ty = t >> 4;
    const int i0 = blockIdx.y * 128;
    const int j0 = blockIdx.x * 128;

    // housekeeping (visible to k_mst via launch-order dependency)
    if (blockIdx.y == 0) {
        if (blockIdx.x == 0 && t < NBLK) g_bar_flag[t] = 0;
        if (blockIdx.x == 0 && t == 0) g_bar_gen = 0;
        for (int e = t; e < 384; e += 256)
            g_best[e >> 7][blockIdx.x * 128 + (e & 127)] = ~0ull;
    }

    const int lr = t >> 1;
    const int lc = (t & 1) * 16;

    unsigned long long acc2[8][4];
#pragma unroll
    for (int m = 0; m < 8; m++)
#pragma unroll
        for (int n = 0; n < 4; n++) acc2[m][n] = 0ull;

    float na = 0.f, nb = 0.f;            // register norm partials (32 cols each)

#pragma unroll
    for (int k0 = 0; k0 < DIM; k0 += 32) {
#pragma unroll
        for (int q = 0; q < 4; q++) {
            int c = lc + q * 4;
            float4 va = *(const float4*)(p + (size_t)(i0 + lr) * DIM + k0 + c);
            As[c + 0][lr] = va.x; As[c + 1][lr] = va.y;
            As[c + 2][lr] = va.z; As[c + 3][lr] = va.w;
            na = fmaf(va.x, va.x, na); na = fmaf(va.y, va.y, na);
            na = fmaf(va.z, va.z, na); na = fmaf(va.w, va.w, na);
            float4 vb = *(const float4*)(p + (size_t)(j0 + lr) * DIM + k0 + c);
            Bs[c + 0][lr] = vb.x; Bs[c + 1][lr] = vb.y;
            Bs[c + 2][lr] = vb.z; Bs[c + 3][lr] = vb.w;
            nb = fmaf(vb.x, vb.x, nb); nb = fmaf(vb.y, vb.y, nb);
            nb = fmaf(vb.z, vb.z, nb); nb = fmaf(vb.w, vb.w, nb);
        }
        __syncthreads();

#pragma unroll
        for (int k = 0; k < 32; k++) {
            uint4 a0 = *(const uint4*)&As[k][ty * 8];
            uint4 a1 = *(const uint4*)&As[k][ty * 8 + 4];
            unsigned au[8] = {a0.x, a0.y, a0.z, a0.w, a1.x, a1.y, a1.z, a1.w};
            ulonglong2 b0 = *(const ulonglong2*)&Bs[k][tx * 8];
            ulonglong2 b1 = *(const ulonglong2*)&Bs[k][tx * 8 + 4];
            unsigned long long bp[4] = {b0.x, b0.y, b1.x, b1.y};
#pragma unroll
            for (int m = 0; m < 8; m++) {
                unsigned long long ap;
                asm("mov.b64 %0, {%1, %1};" : "=l"(ap) : "r"(au[m]));
#pragma unroll
                for (int n = 0; n < 4; n++)
                    asm("fma.rn.f32x2 %0, %1, %2, %0;"
                        : "+l"(acc2[m][n]) : "l"(ap), "l"(bp[n]));
            }
        }
        __syncthreads();
    }

    // pair the two loader threads of each row (t and t^1 cover disjoint cols)
    na += __shfl_xor_sync(0xFFFFFFFFu, na, 1);
    nb += __shfl_xor_sync(0xFFFFFFFFu, nb, 1);
    if ((t & 1) == 0) { sAsq[lr] = na; sBsq[lr] = nb; }
    __syncthreads();

    float sqi[8], sqj[8];
#pragma unroll
    for (int m = 0; m < 8; m++) sqi[m] = sAsq[ty * 8 + m];
#pragma unroll
    for (int n = 0; n < 8; n++) sqj[n] = sBsq[tx * 8 + n];

#pragma unroll
    for (int m = 0; m < 8; m++) {
        const int row = i0 + ty * 8 + m;
        float o[8];
#pragma unroll
        for (int n = 0; n < 4; n++) {
            unsigned lo, hi;
            asm("mov.b64 {%0, %1}, %2;" : "=r"(lo), "=r"(hi) : "l"(acc2[m][n]));
            float d0 = __uint_as_float(lo), d1 = __uint_as_float(hi);
            o[2 * n + 0] = fmaxf(sqi[m] + sqj[2 * n + 0] - 2.f * d0, 0.f);
            o[2 * n + 1] = fmaxf(sqi[m] + sqj[2 * n + 1] - 2.f * d1, 0.f);
        }
        float* dst = g_d2 + (size_t)row * NPTS + j0 + tx * 8;
        *(float4*)(dst)     = *(float4*)(o);
        *(float4*)(dst + 4) = *(float4*)(o + 4);

        // fused per-(row, 128-col block) min (w<<32|j), diag excluded
        unsigned long long key = ~0ull;
#pragma unroll
        for (int n = 0; n < 8; n++) {
            unsigned jj = (unsigned)(j0 + tx * 8 + n);
            if (jj != (unsigned)row)
                key = umin64(key, ((unsigned long long)__float_as_uint(o[n]) << 32) | jj);
        }
#pragma unroll
        for (int s = 8; s > 0; s >>= 1)
            key = umin64(key, __shfl_down_sync(0xFFFFFFFFu, key, s, 16));
        if (tx == 0) g_bmin[row * 32 + blockIdx.x] = key;
    }
}

// ---------------------------------------------------------------------------
// Kernel 2: persistent Boruvka + distributed rank-sort.
// Selection per warp/row: exact per-row cache (valid while its partner stays
// out-of-component), falling back to block-min bounds with rescans (exact ==
// full-scan). One grid barrier per round; hook over active components, all
// blocks redundantly in their own shared memory. All blocks stay alive and
// rank-sort the 4095 lengths cooperatively at the end (one edge per warp).
// ---------------------------------------------------------------------------
__global__ void __launch_bounds__(TPB, 1) k_mst(float* __restrict__ out) {
    __shared__ unsigned short comp[NPTS];     // 8 KB persistent labels
    __shared__ int par[NPTS];                 // 16 KB; reused as rank-sort buf
    __shared__ unsigned short act[2][NPTS];   // 16 KB ping-pong active comps
    __shared__ int s_na2;                     // next active count
    __shared__ int s_cnt;                     // block0 edge counter

    const int t    = threadIdx.x;
    const int wid  = t >> 5;
    const int lane = t & 31;
    const int row  = blockIdx.x * 32 + wid;

    for (int i = t; i < NPTS; i += TPB) {
        comp[i] = (unsigned short)i;
        act[0][i] = (unsigned short)i;
    }
    if (t == 0) s_cnt = 0;
    __syncthreads();

    unsigned long long rowcache = ~0ull;   // warp-uniform exact row best
    int na = NPTS;
    int gen = 0;

    for (int k = 0; k < 12; k++) {
        const int pp = k & 1;

        // ---- selection: cache hit, else block-min bounds ----
        {
            const unsigned myc = comp[row];
            bool hit = (rowcache != ~0ull) &&
                       (comp[(unsigned)(rowcache & 0xFFFFu)] != myc);
            unsigned long long best;
            if (hit) {
                best = rowcache;            // provably still the exact row min
            } else {
                unsigned long long e = g_bmin[row * 32 + lane];
                unsigned ej = (unsigned)(e & 0xFFFFu);
                bool oc = comp[ej] != myc;
                unsigned long long cand = oc ? e : ~0ull;
#pragma unroll
                for (int s = 16; s > 0; s >>= 1)
                    cand = umin64(cand, __shfl_xor_sync(0xFFFFFFFFu, cand, s));

                unsigned scanmask = __ballot_sync(0xFFFFFFFFu, !oc && e < cand);
                best = cand;
                while (scanmask) {
                    int b = __ffs(scanmask) - 1;
                    scanmask &= scanmask - 1;
                    const float* r = g_d2 + (size_t)row * NPTS + b * 128;
#pragma unroll
                    for (int s2 = 0; s2 < 4; s2++) {
                        int jj = s2 * 32 + lane;
                        if (comp[b * 128 + jj] != myc) {
                            unsigned long long kk =
                                ((unsigned long long)__float_as_uint(r[jj]) << 32) |
                                (unsigned)(b * 128 + jj);
                            best = umin64(best, kk);
                        }
                    }
                }
#pragma unroll
                for (int s = 16; s > 0; s >>= 1)
                    best = umin64(best, __shfl_down_sync(0xFFFFFFFFu, best, s));
                best = __shfl_sync(0xFFFFFFFFu, best, 0);   // broadcast
                rowcache = best;
            }
            if (lane == 0 && best != ~0ull)
                atomicMin(&g_best[k % 3][myc], loc2key(best, (unsigned)row));
        }
        gridbar(++gen);

        // ---- hook over ACTIVE components (all blocks, redundant) ----
        const unsigned long long* B = g_best[k % 3];
        for (int idx = t; idx < na; idx += TPB) { int c = act[pp][idx]; par[c] = c; }
        if (t == 0) s_na2 = 0;
        __syncthreads();

        for (int idx = t; idx < na; idx += TPB) {
            int c = act[pp][idx];
            unsigned long long key = B[c];
            bool isroot = false;
            if (key != ~0ull) {
                unsigned id = (unsigned)(key & 0xFFFFFFu);
                int u = (int)(id >> 12), v = (int)(id & 0xFFFu);
                int cu = comp[u], cv = comp[v];
                int other = (cu == c) ? cv : cu;
                bool mutual = (B[other] == key);
                if (!mutual)        par[c] = other;
                else if (c > other) par[c] = other;
                else                isroot = true;
                if (blockIdx.x == 0 && (!mutual || c < other)) {
                    int e = atomicAdd(&s_cnt, 1);
                    g_len[e] = sqrtf(__uint_as_float((unsigned)(key >> 24)));
                }
            } else {
                isroot = true;
            }
            if (isroot) {
                int pos = atomicAdd(&s_na2, 1);
                act[pp ^ 1][pos] = (unsigned short)c;
            }
        }
        __syncthreads();

        // pointer jumping over active list, early exit on convergence
        for (int it = 0; it < 12; it++) {
            int chg = 0;
            for (int idx = t; idx < na; idx += TPB) {
                int c = act[pp][idx];
                int p1 = par[c];
                int p2 = par[p1];
                if (p2 != p1) { par[c] = p2; chg = 1; }
            }
            if (!__syncthreads_or(chg)) break;
        }

        // relabel all vertices + clear this block's slice of buffer (k+2)%3
        for (int i = t; i < NPTS; i += TPB)
            comp[i] = (unsigned short)par[comp[i]];
        if (t < 32) g_best[(k + 2) % 3][blockIdx.x * 32 + t] = ~0ull;
        __syncthreads();

        na = s_na2;
        if (na <= 1) break;
    }

    // ---- distributed rank-sort: all blocks alive, one edge per warp ----
    gridbar(++gen);                        // g_len complete + visible

    float* sh = (float*)par;               // stage lengths in shared
    for (int i = t; i < NPTS - 1; i += TPB) sh[i] = g_len[i];
    __syncthreads();

    const int e = blockIdx.x * 32 + wid;   // 128 blocks x 32 warps = 4096
    if (e < NPTS - 1) {
        unsigned my = __float_as_uint(sh[e]);   // nonneg floats: u32 order
        int r = 0;
        for (int s = lane; s < NPTS - 1; s += 32) {   // stride 32: no conflicts
            unsigned o = __float_as_uint(sh[s]);
            r += (o < my) || (o == my && s < e);
        }
#pragma unroll
        for (int s = 16; s > 0; s >>= 1)
            r += __shfl_down_sync(0xFFFFFFFFu, r, s);
        if (lane == 0) out[r] = __uint_as_float(my);
    }
}

// ---------------------------------------------------------------------------
extern "C" void kernel_launch(void* const* d_in, const int* in_sizes, int n_in,
                              void* d_out, int out_size) {
    (void)in_sizes; (void)n_in; (void)out_size;
    const float* points = (const float*)d_in[0];
    float* out = (float*)d_out;

    k_d2<<<dim3(NPTS / 128, NPTS / 128), 256>>>(points);  // 32x32 x 256
    k_mst<<<NBLK, TPB>>>(out);
}